// round 3
// baseline (speedup 1.0000x reference)
#include <cuda_runtime.h>

// Problem constants
constexpr int Bn = 8;      // batch
constexpr int C  = 64;     // cin
constexpr int O  = 64;     // cout
constexpr int OL = 60;     // cout_lin
constexpr int H  = 256;
constexpr int W  = 256;
constexpr int R  = Bn * C * H;   // 131072 rows for forward dft-w
constexpr int R2 = Bn * O * H;   // 131072 rows for inverse dft-w
constexpr int NMODE = 32 * 16;   // 512 active modes (32 ky x 16 kx)

// Scratch (static device globals; allocation-free)
__device__ __align__(16) float  g_X1[R * 32];              // [row][16 kx][re,im]
__device__ __align__(16) float2 g_XF[Bn * C * 32 * 16];    // [b][c][j][kx]
__device__ __align__(16) float2 g_WT[NMODE * C * OL];      // [mode][i][o]
__device__ __align__(16) float2 g_OF[Bn * O * 32 * 16];    // [b][o][j][kx]
__device__ __align__(16) float2 g_Y1[Bn * O * H * 16];     // [b][o][h][kx]
__device__ __align__(16) float  g_B1[256 * 32];            // fwd dft-w twiddles [w][2k|2k+1]
__device__ __align__(16) float  g_T5A[16 * 128];           // inv dft-w cos coeffs
__device__ __align__(16) float  g_T5B[16 * 128];           // inv dft-w sin coeffs

// ---------------------------------------------------------------------------
// K0a: twiddle tables
// ---------------------------------------------------------------------------
__global__ void k_tables() {
    int t = blockIdx.x * blockDim.x + threadIdx.x;
    if (t < 256 * 32) {
        int w = t >> 5, j = t & 31, k = j >> 1;
        float s, c;
        sincospif((float)(k * w) / 128.0f, &s, &c);
        g_B1[t] = (j & 1) ? -s : c;          // e^{-i2pi k w/256}: re at 2k, im at 2k+1
    } else if (t < 256 * 32 + 16 * 128) {
        int u = t - 256 * 32;
        int k = u >> 7, w = u & 127;
        float s, c;
        sincospif((float)(k * w) / 128.0f, &s, &c);
        if (k == 0) { g_T5A[u] = 1.0f / 256.0f; g_T5B[u] = 0.0f; }
        else        { g_T5A[u] = 2.0f * c / 256.0f; g_T5B[u] = -2.0f * s / 256.0f; }
    }
}

// ---------------------------------------------------------------------------
// K0b: transpose weights into per-mode [i][o] complex layout (coalesced reads)
// ---------------------------------------------------------------------------
__global__ void k_wt(const float* __restrict__ w1r, const float* __restrict__ w1i,
                     const float* __restrict__ w2r, const float* __restrict__ w2i) {
    int n = C * OL * 256;  // 983040 per tensor
    int t = blockIdx.x * blockDim.x + threadIdx.x;
    if (t >= 2 * n) return;
    int half = (t >= n);
    int s = half ? t - n : t;
    const float* wr = half ? w2r : w1r;
    const float* wi = half ? w2i : w1i;
    int i   = s / (OL * 256);
    int rem = s - i * (OL * 256);
    int o   = rem >> 8;
    int xy  = rem & 255;
    int x = xy >> 4, y = xy & 15;
    int mode = ((half ? (16 + x) : x) << 4) + y;
    g_WT[((size_t)mode * C + i) * OL + o] = make_float2(wr[s], wi[s]);
}

// ---------------------------------------------------------------------------
// K1: forward partial DFT along w.  X1[row][k] = sum_w x[row][w] e^{-i2pi kw/256}
// Register-tiled real GEMM: [64 rows x 32 cols] per block, 4x4 per thread.
// ---------------------------------------------------------------------------
__global__ __launch_bounds__(128) void k_dftw(const float* __restrict__ x) {
    __shared__ __align__(16) float Bs[256 * 32];   // full twiddle matrix
    __shared__ float As[64][33];                    // A chunk, padded
    int t = threadIdx.x;
    size_t row0 = (size_t)blockIdx.x * 64;

    {   // stage twiddle table once
        const float4* src = (const float4*)g_B1;
        float4* dst = (float4*)Bs;
        for (int i = t; i < 2048; i += 128) dst[i] = src[i];
    }
    int tr = t >> 3, tc = t & 7;
    int r0 = tr * 4, c0 = tc * 4;
    float acc[4][4] = {};

    for (int wc = 0; wc < 256; wc += 32) {
        __syncthreads();
        #pragma unroll
        for (int it = 0; it < 4; it++) {
            int row = (t >> 3) + it * 16;
            int kk4 = (t & 7) * 4;
            float4 v = *(const float4*)&x[(row0 + row) * 256 + wc + kk4];
            As[row][kk4 + 0] = v.x; As[row][kk4 + 1] = v.y;
            As[row][kk4 + 2] = v.z; As[row][kk4 + 3] = v.w;
        }
        __syncthreads();
        #pragma unroll
        for (int kk = 0; kk < 32; kk++) {
            float4 b = *(const float4*)&Bs[(wc + kk) * 32 + c0];
            float a0 = As[r0 + 0][kk], a1 = As[r0 + 1][kk];
            float a2 = As[r0 + 2][kk], a3 = As[r0 + 3][kk];
            acc[0][0] += a0 * b.x; acc[0][1] += a0 * b.y; acc[0][2] += a0 * b.z; acc[0][3] += a0 * b.w;
            acc[1][0] += a1 * b.x; acc[1][1] += a1 * b.y; acc[1][2] += a1 * b.z; acc[1][3] += a1 * b.w;
            acc[2][0] += a2 * b.x; acc[2][1] += a2 * b.y; acc[2][2] += a2 * b.z; acc[2][3] += a2 * b.w;
            acc[3][0] += a3 * b.x; acc[3][1] += a3 * b.y; acc[3][2] += a3 * b.z; acc[3][3] += a3 * b.w;
        }
    }
    #pragma unroll
    for (int rr = 0; rr < 4; rr++) {
        float4 v = make_float4(acc[rr][0], acc[rr][1], acc[rr][2], acc[rr][3]);
        *(float4*)&g_X1[(row0 + r0 + rr) * 32 + c0] = v;
    }
}

// ---------------------------------------------------------------------------
// K2: forward partial DFT along h at the 32 active rows (ky in 0..15, 240..255).
// One block per (b,c); thread (k,j) accumulates over 256 h with twiddle recurrence.
// ---------------------------------------------------------------------------
__global__ __launch_bounds__(512) void k_dfth() {
    __shared__ __align__(16) float2 Xs[256][16];
    int bc = blockIdx.x;
    int t = threadIdx.x;
    {
        const float4* src = (const float4*)(g_X1 + (size_t)bc * 8192);
        float4* dst = (float4*)Xs;
        for (int i = t; i < 2048; i += 512) dst[i] = src[i];
    }
    __syncthreads();
    int k = t >> 5, j = t & 31;                 // warp owns a fixed k -> Xs broadcast
    int ky = (j < 16) ? j : (224 + j);          // j>=16 -> ky = 240 + (j-16)
    float sr, cr;
    sincospif(-(float)ky / 128.0f, &sr, &cr);   // per-step rotation e^{-i2pi ky/256}
    float c = 1.0f, s = 0.0f, ar = 0.0f, ai = 0.0f;
    #pragma unroll 8
    for (int h = 0; h < 256; h++) {
        float2 xv = Xs[h][k];
        ar += xv.x * c - xv.y * s;
        ai += xv.x * s + xv.y * c;
        float nc = c * cr - s * sr;
        s = c * sr + s * cr;
        c = nc;
    }
    g_XF[((size_t)bc * 32 + j) * 16 + k] = make_float2(ar, ai);
}

// ---------------------------------------------------------------------------
// K3: per-mode complex channel mixing [8x64]@[64x60] + pair products (ch 60..63)
// ---------------------------------------------------------------------------
__global__ __launch_bounds__(512) void k_mix() {
    __shared__ float2 Xs[512];          // [b*64+i]
    __shared__ float2 Ws[C * OL];       // [i*60+o]
    __shared__ float2 Os[8 * OL];
    int m = blockIdx.x;                 // mode = j*16+k
    int j = m >> 4, k = m & 15;
    int t = threadIdx.x;

    Xs[t] = g_XF[(size_t)t * 512 + m];  // [b*64+i][j][k] gather
    const float2* wsrc = g_WT + (size_t)m * C * OL;
    for (int i = t; i < C * OL; i += 512) Ws[i] = wsrc[i];
    __syncthreads();

    if (t < 480) {
        int b = t / 60, o = t - b * 60;
        const float2* xp = &Xs[b * 64];
        float ar = 0.0f, ai = 0.0f;
        #pragma unroll 8
        for (int i = 0; i < 64; i++) {
            float2 xv = xp[i];
            float2 wv = Ws[i * OL + o];
            ar += xv.x * wv.x - xv.y * wv.y;
            ai += xv.x * wv.y + xv.y * wv.x;
        }
        Os[t] = make_float2(ar, ai);
        g_OF[((size_t)(b * O + o) * 32 + j) * 16 + k] = make_float2(ar, ai);
    }
    __syncthreads();
    if (t < 32) {
        int b = t >> 2, p = t & 3;
        float2 u = Os[b * 60 + 2 * p];
        float2 v = Os[b * 60 + 2 * p + 1];
        float2 pr = make_float2(u.x * v.x - u.y * v.y, u.x * v.y + u.y * v.x);
        g_OF[((size_t)(b * O + 60 + p) * 32 + j) * 16 + k] = pr;
    }
}

// ---------------------------------------------------------------------------
// K4: inverse DFT along h.  Y1[h][k] = (1/256) sum_j OF[j][k] e^{+i2pi ky(j) h/256}
// One block per (b,o); thread = h; 16 complex accumulators.
// ---------------------------------------------------------------------------
__global__ __launch_bounds__(256) void k_idfth() {
    __shared__ __align__(16) float2 OFs[32][16];
    int bo = blockIdx.x;
    int h = threadIdx.x;
    {
        const float4* src = (const float4*)(g_OF + (size_t)bo * 512);
        float4* dst = (float4*)OFs;
        for (int i = h; i < 256; i += 256) dst[i] = src[i];
    }
    __syncthreads();
    float2 acc[16];
    #pragma unroll
    for (int k = 0; k < 16; k++) acc[k] = make_float2(0.0f, 0.0f);
    #pragma unroll 4
    for (int j = 0; j < 32; j++) {
        int ky = (j < 16) ? j : (224 + j);
        float s, c;
        sincospif((float)(ky * h) / 128.0f, &s, &c);   // e^{+i2pi ky h/256}
        #pragma unroll
        for (int k = 0; k < 16; k++) {
            float2 ov = OFs[j][k];
            acc[k].x += ov.x * c - ov.y * s;
            acc[k].y += ov.x * s + ov.y * c;
        }
    }
    float2* outp = g_Y1 + ((size_t)bo * 256 + h) * 16;
    #pragma unroll
    for (int k = 0; k < 16; k++)
        outp[k] = make_float2(acc[k].x * (1.0f / 256.0f), acc[k].y * (1.0f / 256.0f));
}

// ---------------------------------------------------------------------------
// K5: inverse real DFT along w (c2r semantics: imag of DC/Nyquist ignored).
// Even/odd symmetry: compute w and 256-w together -> half the FMAs.
// Block handles 32 rows; thread = w in 0..127.
// ---------------------------------------------------------------------------
__global__ __launch_bounds__(128) void k_idftw(float* __restrict__ out) {
    __shared__ __align__(16) float Ta[16 * 128];
    __shared__ __align__(16) float Tb[16 * 128];
    __shared__ __align__(16) float2 Ys[32][16];
    int t = threadIdx.x;
    size_t row0 = (size_t)blockIdx.x * 32;
    {
        const float4* sa = (const float4*)g_T5A;
        const float4* sb = (const float4*)g_T5B;
        float4* da = (float4*)Ta; float4* db = (float4*)Tb;
        for (int i = t; i < 512; i += 128) { da[i] = sa[i]; db[i] = sb[i]; }
        const float4* sy = (const float4*)(g_Y1 + row0 * 16);
        float4* dy = (float4*)Ys;
        for (int i = t; i < 256; i += 128) dy[i] = sy[i];
    }
    __syncthreads();
    float Ar[16], Br[16];
    #pragma unroll
    for (int k = 0; k < 16; k++) { Ar[k] = Ta[k * 128 + t]; Br[k] = Tb[k * 128 + t]; }

    for (int r = 0; r < 32; r++) {
        float E = 0.0f, Od = 0.0f;
        #pragma unroll
        for (int k = 0; k < 16; k++) {
            float2 y = Ys[r][k];
            E  += y.x * Ar[k];   // even (cos) part
            Od += y.y * Br[k];   // odd (sin) part
        }
        float* op = out + (row0 + r) * 256;
        op[t] = E + Od;
        if (t > 0) {
            op[256 - t] = E - Od;
        } else {
            float E128 = 0.0f;   // w = 128 (Nyquist column of the output grid)
            #pragma unroll
            for (int k = 0; k < 16; k++) {
                float a = (k == 0) ? (1.0f / 256.0f)
                                   : ((k & 1) ? (-2.0f / 256.0f) : (2.0f / 256.0f));
                E128 += Ys[r][k].x * a;
            }
            op[128] = E128;
        }
    }
}

// ---------------------------------------------------------------------------
extern "C" void kernel_launch(void* const* d_in, const int* in_sizes, int n_in,
                              void* d_out, int out_size) {
    const float* x   = (const float*)d_in[0];
    const float* w1r = (const float*)d_in[1];
    const float* w1i = (const float*)d_in[2];
    const float* w2r = (const float*)d_in[3];
    const float* w2i = (const float*)d_in[4];
    float* out = (float*)d_out;

    k_tables<<<(256 * 32 + 16 * 128 + 255) / 256, 256>>>();
    k_wt<<<(2 * C * OL * 256 + 255) / 256, 256>>>(w1r, w1i, w2r, w2i);
    k_dftw<<<R / 64, 128>>>(x);
    k_dfth<<<Bn * C, 512>>>();
    k_mix<<<NMODE, 512>>>();
    k_idfth<<<Bn * O, 256>>>();
    k_idftw<<<R2 / 32, 128>>>(out);
}